// round 9
// baseline (speedup 1.0000x reference)
#include <cuda_runtime.h>
#include <cuda_fp16.h>

#define B 32
#define T 32
#define IDIM 8192
#define H 8192
#define ODIM 2048
#define NNZ_HH 1048576
#define NNZ_IH 524288
#define NNZ_HO 262144

#define RBLOCKS 148
#define RTHREADS 1024
#define RWARPS ((RBLOCKS * RTHREADS) / 32)   // 4736
#define NSINGLE (2 * RWARPS - H)             // 1280 warps carry one row

// ---------------- device scratch (static, zero-init at load) ----------------
__device__ __half g_xTh[(size_t)T * IDIM * B];    // (t, i, b) fp16
__device__ __half g_preH[(size_t)T * H * B];      // hh_bias + ih@x_t (fp16)
__device__ __half g_hsH[T + 1][H * B];            // h_0..h_T fp16
__device__ float  g_outT[(size_t)T * ODIM * B];   // (t, o, b)
__device__ int    g_cntHH[H];
__device__ int    g_cntIH[H];
__device__ int    g_cntHO[ODIM];
__device__ unsigned g_arrive;
__device__ unsigned g_cursor;
__device__ int    g_order[H];                     // hh rows sorted by nnz asc

__device__ int      g_hh_ptr[H + 1];
__device__ unsigned g_hh_pair[NNZ_HH];   // packed: col<<16 | fp16(val)
__device__ int      g_ih_ptr[H + 1];
__device__ unsigned g_ih_pair[NNZ_IH];
__device__ int      g_ho_ptr[ODIM + 1];
__device__ unsigned g_ho_pair[NNZ_HO];

// ---------------- launch 1: histograms + x transpose->fp16 ------------------
#define HIST_BLOCKS (NNZ_HH / 256)
__global__ void hist_prep_kernel(const int* __restrict__ hh_rows,
                                 const int* __restrict__ ih_rows,
                                 const int* __restrict__ ho_rows,
                                 const float* __restrict__ x) {
    if (blockIdx.x < HIST_BLOCKS) {
        int i = blockIdx.x * 256 + threadIdx.x;
        atomicAdd(&g_cntHH[hh_rows[i]], 1);
        if (i < NNZ_IH) atomicAdd(&g_cntIH[ih_rows[i]], 1);
        if (i < NNZ_HO) atomicAdd(&g_cntHO[ho_rows[i]], 1);
        return;
    }
    __shared__ float tile[32][33];
    int bi = blockIdx.x - HIST_BLOCKS;
    int t  = bi >> 8;
    int i0 = (bi & 255) << 5;
    int tx = threadIdx.x & 31;
    int ty = threadIdx.x >> 5;
    for (int bb = ty; bb < 32; bb += 8)
        tile[bb][tx] = x[(size_t)bb * T * IDIM + (size_t)t * IDIM + i0 + tx];
    __syncthreads();
    for (int ii = ty; ii < 32; ii += 8)
        g_xTh[(size_t)t * IDIM * B + (size_t)(i0 + ii) * B + tx] = __float2half(tile[tx][ii]);
}

// ---------------- launch 2: scan cnt -> ptr, re-zero cnt --------------------
__global__ void scan_all_kernel() {
    __shared__ int s[1024];
    int* cnt; int* ptr; int n;
    if (blockIdx.x == 0)      { cnt = g_cntHH; ptr = g_hh_ptr; n = H; }
    else if (blockIdx.x == 1) { cnt = g_cntIH; ptr = g_ih_ptr; n = H; }
    else                      { cnt = g_cntHO; ptr = g_ho_ptr; n = ODIM; }
    int tid = threadIdx.x;
    int per = (n + 1023) >> 10;
    int base = tid * per;
    int local[8];
    int sum = 0;
    for (int j = 0; j < per; j++) {
        int v = (base + j < n) ? cnt[base + j] : 0;
        local[j] = sum;
        sum += v;
    }
    s[tid] = sum;
    __syncthreads();
    for (int off = 1; off < 1024; off <<= 1) {
        int v = (tid >= off) ? s[tid - off] : 0;
        __syncthreads();
        s[tid] += v;
        __syncthreads();
    }
    int excl = tid ? s[tid - 1] : 0;
    for (int j = 0; j < per; j++)
        if (base + j < n) ptr[base + j] = excl + local[j];
    if (tid == 1023) ptr[n] = s[1023];
    __syncthreads();
    for (int j = 0; j < per; j++)
        if (base + j < n) cnt[base + j] = 0;
}

// ---------------- launch 3: scatter COO -> packed CSR + resets ---------------
__device__ __forceinline__ unsigned pack_pair(int col, float val) {
    __half hv = __float2half_rn(val);
    return ((unsigned)col << 16) | (unsigned)__half_as_ushort(hv);
}

__global__ void scatter_all_kernel(const int* __restrict__ hh_rows,
                                   const int* __restrict__ hh_cols,
                                   const float* __restrict__ hh_vals,
                                   const int* __restrict__ ih_rows,
                                   const int* __restrict__ ih_cols,
                                   const float* __restrict__ ih_vals,
                                   const int* __restrict__ ho_rows,
                                   const int* __restrict__ ho_cols,
                                   const float* __restrict__ ho_vals) {
    if (blockIdx.x >= HIST_BLOCKS) {   // 32 aux blocks: zero h0 (fp16) + flags
        int i = (blockIdx.x - HIST_BLOCKS) * 256 + threadIdx.x;   // 0..8191
        uint4* h0 = (uint4*)g_hsH[0];
        uint4 z = make_uint4(0u, 0u, 0u, 0u);
        for (int j = i; j < (H * B) / 8; j += 8192) h0[j] = z;
        if (i == 0) { g_arrive = 0u; g_cursor = 0u; }
        return;
    }
    int i = blockIdx.x * blockDim.x + threadIdx.x;
    {
        int r = hh_rows[i];
        int pos = atomicAdd(&g_cntHH[r], 1);
        g_hh_pair[g_hh_ptr[r] + pos] = pack_pair(hh_cols[i], hh_vals[i]);
    }
    if (i < NNZ_IH) {
        int r = ih_rows[i];
        int pos = atomicAdd(&g_cntIH[r], 1);
        g_ih_pair[g_ih_ptr[r] + pos] = pack_pair(ih_cols[i], ih_vals[i]);
    }
    if (i < NNZ_HO) {
        int r = ho_rows[i];
        int pos = atomicAdd(&g_cntHO[r], 1);
        g_ho_pair[g_ho_ptr[r] + pos] = pack_pair(ho_cols[i], ho_vals[i]);
    }
}

// ---------------- gather core: HFMA2 accumulate -------------------------------
// Layout: sub = lane>>2 (8 concurrent nnz per shuffle-step), bq = lane&3.
// base pointers are pre-offset by bq; offset per nnz is c*4 uint4 (64B row).
__device__ __forceinline__ void hfma8(unsigned u, uint4 g, uint4& ha) {
    unsigned vv = __byte_perm(u, u, 0x1010);   // half2(val, val)
    __half2 v2 = *reinterpret_cast<__half2*>(&vv);
    __half2* a = reinterpret_cast<__half2*>(&ha);
    const __half2* gg = reinterpret_cast<const __half2*>(&g);
    a[0] = __hfma2(v2, gg[0], a[0]);
    a[1] = __hfma2(v2, gg[1], a[1]);
    a[2] = __hfma2(v2, gg[2], a[2]);
    a[3] = __hfma2(v2, gg[3], a[3]);
}

__device__ __forceinline__ void hacc_flush(uint4& ha, float4& lo, float4& hi) {
    float2 f0 = __half22float2(*reinterpret_cast<__half2*>(&ha.x));
    float2 f1 = __half22float2(*reinterpret_cast<__half2*>(&ha.y));
    float2 f2 = __half22float2(*reinterpret_cast<__half2*>(&ha.z));
    float2 f3 = __half22float2(*reinterpret_cast<__half2*>(&ha.w));
    lo.x += f0.x; lo.y += f0.y; lo.z += f1.x; lo.w += f1.y;
    hi.x += f2.x; hi.y += f2.y; hi.z += f3.x; hi.w += f3.y;
    ha = make_uint4(0u, 0u, 0u, 0u);
}

// single stream: full blocks (pipelined pair prefetch) + tail
__device__ __forceinline__ void mono_gather(const unsigned* __restrict__ pair,
                                            int k, int e,
                                            const uint4* __restrict__ base,
                                            int lane, int sub,
                                            float4& lo, float4& hi) {
    uint4 ha = make_uint4(0u, 0u, 0u, 0u);
    int nb = (e - k) >> 5;
    if (nb > 0) {
        unsigned p = __ldg(pair + k + lane);
        for (int i = 0; i < nb; i++) {
            unsigned cur = p;
            if (i + 1 < nb) p = __ldg(pair + k + 32 + lane);
#pragma unroll
            for (int j = 0; j < 4; j++) {
                unsigned u = __shfl_sync(0xffffffffu, cur, (j << 3) + sub);
                uint4 g = __ldg(base + ((u >> 16) << 2));
                hfma8(u, g, ha);
            }
            hacc_flush(ha, lo, hi);
            k += 32;
        }
    }
    int rem = e - k;
    if (rem > 0) {
        unsigned p = (lane < rem) ? __ldg(pair + k + lane) : 0u;
        int nsub = (rem + 7) >> 3;
        for (int j = 0; j < nsub; j++) {
            int idx = (j << 3) + sub;
            unsigned u = __shfl_sync(0xffffffffu, p, idx);
            if (idx >= rem) u = 0u;   // val bits 0 -> contributes 0
            uint4 g = __ldg(base + ((u >> 16) << 2));
            hfma8(u, g, ha);
        }
        hacc_flush(ha, lo, hi);
    }
}

// dual stream: joint blocks (8 gather LDGs in flight) then per-stream leftovers
__device__ __forceinline__ void dual_gather(const unsigned* __restrict__ pair,
                                            int k0, int e0, const uint4* __restrict__ b0,
                                            int k1, int e1, const uint4* __restrict__ b1,
                                            int lane, int sub,
                                            float4& lo0, float4& hi0,
                                            float4& lo1, float4& hi1) {
    int nj = min((e0 - k0) >> 5, (e1 - k1) >> 5);
    if (nj > 0) {
        uint4 ha0 = make_uint4(0u, 0u, 0u, 0u), ha1 = ha0;
        unsigned p0 = __ldg(pair + k0 + lane);
        unsigned p1 = __ldg(pair + k1 + lane);
        for (int i = 0; i < nj; i++) {
            unsigned c0 = p0, c1 = p1;
            if (i + 1 < nj) {
                p0 = __ldg(pair + k0 + 32 + lane);
                p1 = __ldg(pair + k1 + 32 + lane);
            }
#pragma unroll
            for (int j = 0; j < 4; j++) {
                unsigned u0 = __shfl_sync(0xffffffffu, c0, (j << 3) + sub);
                unsigned u1 = __shfl_sync(0xffffffffu, c1, (j << 3) + sub);
                uint4 g0 = __ldg(b0 + ((u0 >> 16) << 2));
                uint4 g1 = __ldg(b1 + ((u1 >> 16) << 2));
                hfma8(u0, g0, ha0);
                hfma8(u1, g1, ha1);
            }
            hacc_flush(ha0, lo0, hi0);
            hacc_flush(ha1, lo1, hi1);
            k0 += 32; k1 += 32;
        }
    }
    mono_gather(pair, k0, e0, b0, lane, sub, lo0, hi0);
    mono_gather(pair, k1, e1, b1, lane, sub, lo1, hi1);
}

// reduce across 8 sub groups (xor 4, 8, 16)
__device__ __forceinline__ void xreduce8(float4& lo, float4& hi) {
#pragma unroll
    for (int m = 4; m <= 16; m <<= 1) {
        lo.x += __shfl_xor_sync(0xffffffffu, lo.x, m);
        lo.y += __shfl_xor_sync(0xffffffffu, lo.y, m);
        lo.z += __shfl_xor_sync(0xffffffffu, lo.z, m);
        lo.w += __shfl_xor_sync(0xffffffffu, lo.w, m);
        hi.x += __shfl_xor_sync(0xffffffffu, hi.x, m);
        hi.y += __shfl_xor_sync(0xffffffffu, hi.y, m);
        hi.z += __shfl_xor_sync(0xffffffffu, hi.z, m);
        hi.w += __shfl_xor_sync(0xffffffffu, hi.w, m);
    }
}

__device__ __forceinline__ uint4 pack8h(float4 lo, float4 hi) {
    __half2 a = __floats2half2_rn(lo.x, lo.y);
    __half2 b = __floats2half2_rn(lo.z, lo.w);
    __half2 c = __floats2half2_rn(hi.x, hi.y);
    __half2 d = __floats2half2_rn(hi.z, hi.w);
    uint4 u;
    u.x = *reinterpret_cast<unsigned*>(&a);
    u.y = *reinterpret_cast<unsigned*>(&b);
    u.z = *reinterpret_cast<unsigned*>(&c);
    u.w = *reinterpret_cast<unsigned*>(&d);
    return u;
}

#define F4Z make_float4(0.f, 0.f, 0.f, 0.f)

// ---------------- launch 4: fused ih + recurrence (persistent) --------------
__global__ void __launch_bounds__(RTHREADS, 1)
recur_kernel(const float* __restrict__ hhb) {
    __shared__ int bins[512];
    __shared__ int scn[512];
    int tid = threadIdx.x;
    int lane = tid & 31;
    int sub = lane >> 2, bq = lane & 3;
    int gw = blockIdx.x * (RTHREADS / 32) + (tid >> 5);
    unsigned target = 0;

    // ---- phase 0a: block 0 counting-sorts hh rows by length (ascending) ----
    if (blockIdx.x == 0) {
        if (tid < 512) bins[tid] = 0;
        __syncthreads();
        for (int r = tid; r < H; r += RTHREADS) {
            int c = g_hh_ptr[r + 1] - g_hh_ptr[r];
            atomicAdd(&bins[c < 511 ? c : 511], 1);
        }
        __syncthreads();
        if (tid < 512) scn[tid] = bins[tid];
        __syncthreads();
        for (int off = 1; off < 512; off <<= 1) {
            int v = (tid < 512 && tid >= off) ? scn[tid - off] : 0;
            __syncthreads();
            if (tid < 512) scn[tid] += v;
            __syncthreads();
        }
        if (tid < 512) bins[tid] = tid ? scn[tid - 1] : 0;
        __syncthreads();
        for (int r = tid; r < H; r += RTHREADS) {
            int c = g_hh_ptr[r + 1] - g_hh_ptr[r];
            int pos = atomicAdd(&bins[c < 511 ? c : 511], 1);
            g_order[pos] = r;
        }
    }

    // ---- phase 0b: ih (all t), two rows jointly per queue slot --------------
    for (;;) {
        unsigned base;
        if (lane == 0) base = atomicAdd(&g_cursor, 32u);
        base = __shfl_sync(0xffffffffu, base, 0);
        if (base >= (unsigned)(T * H)) break;
#pragma unroll 1
        for (int q = 0; q < 32; q += 2) {
            unsigned wk0 = base + q, wk1 = wk0 + 1;
            int r0 = wk0 & (H - 1), t0 = wk0 >> 13;
            int r1 = wk1 & (H - 1), t1 = wk1 >> 13;
            const uint4* x0 = (const uint4*)(g_xTh + (size_t)t0 * IDIM * B) + bq;
            const uint4* x1 = (const uint4*)(g_xTh + (size_t)t1 * IDIM * B) + bq;
            float4 lo0 = F4Z, hi0 = F4Z, lo1 = F4Z, hi1 = F4Z;
            dual_gather(g_ih_pair, g_ih_ptr[r0], g_ih_ptr[r0 + 1], x0,
                        g_ih_ptr[r1], g_ih_ptr[r1 + 1], x1,
                        lane, sub, lo0, hi0, lo1, hi1);
            xreduce8(lo0, hi0);
            xreduce8(lo1, hi1);
            if (lane < 4) {
                float b0 = __ldg(hhb + r0);
                lo0.x += b0; lo0.y += b0; lo0.z += b0; lo0.w += b0;
                hi0.x += b0; hi0.y += b0; hi0.z += b0; hi0.w += b0;
                ((uint4*)g_preH)[(size_t)wk0 * 4 + lane] = pack8h(lo0, hi0);
                float b1 = __ldg(hhb + r1);
                lo1.x += b1; lo1.y += b1; lo1.z += b1; lo1.w += b1;
                hi1.x += b1; hi1.y += b1; hi1.z += b1; hi1.w += b1;
                ((uint4*)g_preH)[(size_t)wk1 * 4 + lane] = pack8h(lo1, hi1);
            }
        }
    }

    // ---- grid barrier (also publishes g_order) ------------------------------
    __threadfence();
    __syncthreads();
    target += RBLOCKS;
    if (tid == 0) {
        atomicAdd(&g_arrive, 1u);
        while (*(volatile unsigned*)&g_arrive < target) __nanosleep(64);
    }
    __syncthreads();

    // ---- balanced row assignment from sort ----------------------------------
    int r0, r1 = -1;
    if (gw < NSINGLE) {
        r0 = g_order[H - 1 - gw];                    // longest rows -> singles
    } else {
        int i = gw - NSINGLE;
        r0 = g_order[H - NSINGLE - 1 - i];           // long
        r1 = g_order[i];                             // paired with short
    }
    bool two = (r1 >= 0);
    int s0 = g_hh_ptr[r0], e0 = g_hh_ptr[r0 + 1];
    int s1 = 0, e1 = 0;
    if (two) { s1 = g_hh_ptr[r1]; e1 = g_hh_ptr[r1 + 1]; }
    int mid = s0 + ((((e0 - s0) >> 5) >> 1) << 5);   // 32-aligned midpoint of r0

    // ---- T recurrent steps ---------------------------------------------------
    for (int t = 0; t < T; t++) {
        const uint4* hin = (const uint4*)g_hsH[t] + bq;
        uint4* __restrict__ hout4 = (uint4*)g_hsH[t + 1];

        // r0 split into two streams -> 8 gather LDGs in flight
        float4 lo0 = F4Z, hi0 = F4Z, lo1 = F4Z, hi1 = F4Z;
        dual_gather(g_hh_pair, s0, mid, hin, mid, e0, hin,
                    lane, sub, lo0, hi0, lo1, hi1);
        float4 L0, H0;
        L0.x = lo0.x + lo1.x; L0.y = lo0.y + lo1.y;
        L0.z = lo0.z + lo1.z; L0.w = lo0.w + lo1.w;
        H0.x = hi0.x + hi1.x; H0.y = hi0.y + hi1.y;
        H0.z = hi0.z + hi1.z; H0.w = hi0.w + hi1.w;
        xreduce8(L0, H0);

        float4 L1 = F4Z, H1 = F4Z;
        if (two) {
            mono_gather(g_hh_pair, s1, e1, hin, lane, sub, L1, H1);
            xreduce8(L1, H1);
        }

        if (lane < 4) {
            uint4 pu = __ldcg((const uint4*)g_preH + ((size_t)t * H + r0) * 4 + lane);
            float2 q0 = __half22float2(*reinterpret_cast<__half2*>(&pu.x));
            float2 q1 = __half22float2(*reinterpret_cast<__half2*>(&pu.y));
            float2 q2 = __half22float2(*reinterpret_cast<__half2*>(&pu.z));
            float2 q3 = __half22float2(*reinterpret_cast<__half2*>(&pu.w));
            float4 lo, hi;
            lo.x = 1.0f / (1.0f + __expf(-(q0.x + L0.x)));
            lo.y = 1.0f / (1.0f + __expf(-(q0.y + L0.y)));
            lo.z = 1.0f / (1.0f + __expf(-(q1.x + L0.z)));
            lo.w = 1.0f / (1.0f + __expf(-(q1.y + L0.w)));
            hi.x = 1.0f / (1.0f + __expf(-(q2.x + H0.x)));
            hi.y = 1.0f / (1.0f + __expf(-(q2.y + H0.y)));
            hi.z = 1.0f / (1.0f + __expf(-(q3.x + H0.z)));
            hi.w = 1.0f / (1.0f + __expf(-(q3.y + H0.w)));
            hout4[r0 * 4 + lane] = pack8h(lo, hi);
        }
        if (two && lane < 4) {
            uint4 pu = __ldcg((const uint4*)g_preH + ((size_t)t * H + r1) * 4 + lane);
            float2 q0 = __half22float2(*reinterpret_cast<__half2*>(&pu.x));
            float2 q1 = __half22float2(*reinterpret_cast<__half2*>(&pu.y));
            float2 q2 = __half22float2(*reinterpret_cast<__half2*>(&pu.z));
            float2 q3 = __half22float2(*reinterpret_cast<__half2*>(&pu.w));
            float4 lo, hi;
            lo.x = 1.0f / (1.0f + __expf(-(q0.x + L1.x)));
            lo.y = 1.0f / (1.0f + __expf(-(q0.y + L1.y)));
            lo.z = 1.0f / (1.0f + __expf(-(q1.x + L1.z)));
            lo.w = 1.0f / (1.0f + __expf(-(q1.y + L1.w)));
            hi.x = 1.0f / (1.0f + __expf(-(q2.x + H1.x)));
            hi.y = 1.0f / (1.0f + __expf(-(q2.y + H1.y)));
            hi.z = 1.0f / (1.0f + __expf(-(q3.x + H1.z)));
            hi.w = 1.0f / (1.0f + __expf(-(q3.y + H1.w)));
            hout4[r1 * 4 + lane] = pack8h(lo, hi);
        }

        if (t < T - 1) {   // grid barrier
            __threadfence();
            __syncthreads();
            target += RBLOCKS;
            if (tid == 0) {
                atomicAdd(&g_arrive, 1u);
                while (*(volatile unsigned*)&g_arrive < target) __nanosleep(64);
            }
            __syncthreads();
        }
    }
}

// ---------------- launch 5: out = ho @ h_{t+1} (+ counter re-zero) ----------
#define HO_BLOCKS ((T * ODIM) / 8)
__global__ void ho_kernel(const float* __restrict__ hob) {
    if (blockIdx.x >= HO_BLOCKS) {
        int i = (blockIdx.x - HO_BLOCKS) * 256 + threadIdx.x;
        if (i < H) g_cntHH[i] = 0;
        if (i < H) g_cntIH[i] = 0;
        if (i < ODIM) g_cntHO[i] = 0;
        return;
    }
    int w = (blockIdx.x * 256 + threadIdx.x) >> 5;
    int lane = threadIdx.x & 31;
    int sub = lane >> 2, bq = lane & 3;
    int r = w & (ODIM - 1);
    int t = w >> 11;
    const uint4* h4 = (const uint4*)g_hsH[t + 1] + bq;
    int s = g_ho_ptr[r], e = g_ho_ptr[r + 1];
    int mid = s + ((((e - s) >> 5) >> 1) << 5);
    float4 lo0 = F4Z, hi0 = F4Z, lo1 = F4Z, hi1 = F4Z;
    dual_gather(g_ho_pair, s, mid, h4, mid, e, h4, lane, sub, lo0, hi0, lo1, hi1);
    float4 lo, hi;
    lo.x = lo0.x + lo1.x; lo.y = lo0.y + lo1.y;
    lo.z = lo0.z + lo1.z; lo.w = lo0.w + lo1.w;
    hi.x = hi0.x + hi1.x; hi.y = hi0.y + hi1.y;
    hi.z = hi0.z + hi1.z; hi.w = hi0.w + hi1.w;
    xreduce8(lo, hi);
    if (lane < 4) {
        float bias = __ldg(hob + r);
        lo.x += bias; lo.y += bias; lo.z += bias; lo.w += bias;
        hi.x += bias; hi.y += bias; hi.z += bias; hi.w += bias;
        float4* dst = (float4*)g_outT + (size_t)w * 8 + lane * 2;
        dst[0] = lo;
        dst[1] = hi;
    }
}

// ---------------- launch 6: (T,O,B) -> (B,T,O) ------------------------------
__global__ void out_transpose_kernel(float* __restrict__ out) {
    __shared__ float tile[32][33];
    int t  = blockIdx.y;
    int o0 = blockIdx.x * 32;
    int tx = threadIdx.x, ty = threadIdx.y;
    tile[ty][tx] = g_outT[((size_t)t * ODIM + o0 + ty) * B + tx];
    __syncthreads();
    out[(size_t)ty * (T * ODIM) + (size_t)t * ODIM + o0 + tx] = tile[tx][ty];
}

// ---------------- launch ----------------
extern "C" void kernel_launch(void* const* d_in, const int* in_sizes, int n_in,
                              void* d_out, int out_size) {
    const float* x       = (const float*)d_in[0];
    const int*   hh_rows = (const int*)  d_in[1];
    const int*   hh_cols = (const int*)  d_in[2];
    const float* hh_vals = (const float*)d_in[3];
    const float* hh_bias = (const float*)d_in[4];
    const int*   ih_rows = (const int*)  d_in[5];
    const int*   ih_cols = (const int*)  d_in[6];
    const float* ih_vals = (const float*)d_in[7];
    const int*   ho_rows = (const int*)  d_in[8];
    const int*   ho_cols = (const int*)  d_in[9];
    const float* ho_vals = (const float*)d_in[10];
    const float* ho_bias = (const float*)d_in[11];
    float* out = (float*)d_out;

    hist_prep_kernel<<<HIST_BLOCKS + T * (IDIM / 32), 256>>>(hh_rows, ih_rows, ho_rows, x);
    scan_all_kernel<<<3, 1024>>>();
    scatter_all_kernel<<<HIST_BLOCKS + 32, 256>>>(hh_rows, hh_cols, hh_vals,
                                                  ih_rows, ih_cols, ih_vals,
                                                  ho_rows, ho_cols, ho_vals);
    recur_kernel<<<RBLOCKS, RTHREADS>>>(hh_bias);      // launch #4 -> profiled
    ho_kernel<<<HO_BLOCKS + 32, 256>>>(ho_bias);
    out_transpose_kernel<<<dim3(ODIM / 32, T), dim3(32, 32)>>>(out);
}